// round 1
// baseline (speedup 1.0000x reference)
#include <cuda_runtime.h>
#include <cstdint>

// ---------------------------------------------------------------------------
// TT embedding:  VOC = 100*100*100,  EMB = 4*4*8 = 128,  RANK = 16
//   out[tok, n1*32+n2*8+n3] = sum_{r1,r2} core0[i1,n1,r1]*core1[r1,i2,n2,r2]*core2[r2,i3,n3]
// where tok index = i1*10000 + i2*100 + i3, and index 0 (PAD) maps to zeros.
//
// Strategy: precompute G01[i1,i2][(n1*4+n2)*16 + r2] = sum_r1 core0*core1
// (10,000 x 256 fp32 = 10.2 MB, L2-resident), then gather kernel reads
// 1 KB (G01 slice) + 0.5 KB (core2 slice) per token and does 16 FMA/output.
// ---------------------------------------------------------------------------

#define VOC_LL 1000000ULL

// scratch (static __device__ array: allowed, no runtime allocation)
__device__ float g_G01[10000 * 256];

// ---------------------------------------------------------------------------
// Kernel 1: G01 precompute.
// grid = (100 [i2], 10 [group of 10 i1]), block = 256.
// core0: (1,100,4,16)  elem (i1,n1,r1)    @ i1*64 + n1*16 + r1
// core1: (16,100,4,16) elem (r1,i2,n2,r2) @ r1*6400 + i2*64 + n2*16 + r2
// ---------------------------------------------------------------------------
__global__ void __launch_bounds__(256) tt_precompute_g01(
    const float* __restrict__ core0,
    const float* __restrict__ core1)
{
    __shared__ float Bs[1024];   // core1 slice for this i2: [r1][n2*16+r2]
    __shared__ float As[640];    // core0 slices for 10 i1's: [q][n1*16+r1]

    const int i2 = blockIdx.x;   // 0..99
    const int g  = blockIdx.y;   // 0..9  -> i1 in [10g, 10g+10)
    const int t  = threadIdx.x;

    // stage B slice: 64-float contiguous runs per r1 (coalesced)
    #pragma unroll
    for (int j = t; j < 1024; j += 256) {
        const int r1 = j >> 6;
        Bs[j] = core1[r1 * 6400 + i2 * 64 + (j & 63)];
    }
    // stage 10 A slices (contiguous 640 floats)
    #pragma unroll
    for (int j = t; j < 640; j += 256) {
        As[j] = core0[g * 640 + j];
    }
    __syncthreads();

    const int n1   = t >> 6;     // constant within a warp -> As broadcast
    const int rest = t & 63;     // n2*16 + r2; 32 consecutive -> Bs conflict-free

    #pragma unroll
    for (int q = 0; q < 10; q++) {
        float acc = 0.f;
        #pragma unroll
        for (int r1 = 0; r1 < 16; r1++)
            acc += As[q * 64 + n1 * 16 + r1] * Bs[r1 * 64 + rest];
        const int i1 = g * 10 + q;
        g_G01[(i1 * 100 + i2) * 256 + t] = acc;   // 1 KB coalesced store
    }
}

// ---------------------------------------------------------------------------
// Kernel 2: gather. block = 256 threads = 2 tokens (128 threads/token).
// core2: (16,100,8,1) elem (r2,i3,n3) @ r2*800 + i3*8 + n3
// Gs padded to 17-float rows to avoid the stride-64 (2-way) bank conflict.
// ---------------------------------------------------------------------------
__global__ void __launch_bounds__(256) tt_gather(
    const void*  __restrict__ xraw,
    const float* __restrict__ core2,
    float*       __restrict__ out,
    int n_tok)
{
    __shared__ float Gs[2][16 * 17];
    __shared__ float Cs[2][128];

    const int t   = threadIdx.x;
    const int ts  = t >> 7;            // which of the 2 tokens
    const int u   = t & 127;           // output element e = n1*32+n2*8+n3
    const int tok = blockIdx.x * 2 + ts;

    // --- index dtype autodetect (jax may silently emit int32 despite int64) ---
    // If the buffer is int32, a u64 read packs two indices -> >= VOC with
    // overwhelming probability across 4 samples. If int64, all values < VOC.
    const unsigned long long* p64 = (const unsigned long long*)xraw;
    bool is64 = true;
    #pragma unroll
    for (int j = 0; j < 4; j++)
        if (p64[j] >= VOC_LL) is64 = false;

    long long idx = 0;
    if (tok < n_tok) {
        idx = is64 ? ((const long long*)xraw)[tok]
                   : (long long)((const int*)xraw)[tok];
    }

    const int i3  = (int)(idx % 100);
    const int i12 = (int)(idx / 100);  // i1*100 + i2

    if (tok < n_tok) {
        const float* gbase = g_G01 + (size_t)i12 * 256;
        // stage G01 slice (1 KB, fully coalesced), padded layout rows of 17
        Gs[ts][((u)      >> 4) * 17 + ((u)      & 15)] = gbase[u];
        Gs[ts][((u + 128) >> 4) * 17 + ((u + 128) & 15)] = gbase[u + 128];
        // stage core2 slice C[r2][n3] for this i3 (16 x 32B sectors)
        Cs[ts][u] = core2[(u >> 3) * 800 + i3 * 8 + (u & 7)];
    }
    __syncthreads();

    if (tok >= n_tok) return;

    const int row = u >> 3;   // n1*4 + n2
    const int n3  = u & 7;
    float acc = 0.f;
    #pragma unroll
    for (int r2 = 0; r2 < 16; r2++)
        acc += Gs[ts][row * 17 + r2] * Cs[ts][r2 * 8 + n3];

    // PAD_IDX = 0 -> zero row. 512B coalesced store per token.
    out[(size_t)tok * 128 + u] = (idx != 0) ? acc : 0.f;
}

// ---------------------------------------------------------------------------
extern "C" void kernel_launch(void* const* d_in, const int* in_sizes, int n_in,
                              void* d_out, int out_size)
{
    const void*  x     = d_in[0];                 // int64 or int32 indices
    const float* core0 = (const float*)d_in[1];   // (1,100,4,16)
    const float* core1 = (const float*)d_in[2];   // (16,100,4,16)
    const float* core2 = (const float*)d_in[3];   // (16,100,8,1)
    float*       out   = (float*)d_out;

    const int n_tok = in_sizes[0];                // 64*512 = 32768

    tt_precompute_g01<<<dim3(100, 10), 256>>>(core0, core1);
    tt_gather<<<(n_tok + 1) / 2, 256>>>(x, core2, out, n_tok);
}

// round 2
// speedup vs baseline: 1.5333x; 1.5333x over previous
#include <cuda_runtime.h>
#include <cstdint>

// ---------------------------------------------------------------------------
// TT embedding:  VOC = 100^3,  EMB = 4*4*8 = 128,  RANK = 16
//   out[tok, n1*32+n2*8+n3] = sum_{r1,r2} core0[i1,n1,r1]*core1[r1,i2,n2,r2]*core2[r2,i3,n3]
// idx = i1*10000 + i2*100 + i3; idx==0 (PAD) -> zero row.
//
// Kernel 1: G01[i12][n1*64 + n2*16 + r2] = sum_r1 core0*core1  (10.2 MB, L2-resident)
// Kernel 2: warp/token, register-resident contraction with packed f32x2 FMA,
//           no shared memory, no syncthreads.
// ---------------------------------------------------------------------------

#define VOC_LL 1000000ULL

__device__ float g_G01[10000 * 256];

// ---- packed fp32x2 helpers (sm_103a FFMA2) --------------------------------
__device__ __forceinline__ unsigned long long f32x2_fma(
    unsigned long long a, unsigned long long b, unsigned long long c)
{
    unsigned long long d;
    asm("fma.rn.f32x2 %0, %1, %2, %3;" : "=l"(d) : "l"(a), "l"(b), "l"(c));
    return d;
}
__device__ __forceinline__ unsigned long long f32x2_bcast(float x)
{
    unsigned long long d;
    asm("mov.b64 %0, {%1, %1};" : "=l"(d) : "f"(x));
    return d;
}

// ---------------------------------------------------------------------------
// Kernel 1: G01 precompute.  grid=(100 [i2], 10 [i1-group]), block=256.
// core0: (1,100,4,16)  elem (i1,n1,r1)    @ i1*64 + n1*16 + r1
// core1: (16,100,4,16) elem (r1,i2,n2,r2) @ r1*6400 + i2*64 + n2*16 + r2
// Thread t: pair p = t&127 (outputs 2p,2p+1), q-half = t>>7 (5 of 10 i1's).
// ---------------------------------------------------------------------------
__global__ void __launch_bounds__(256) tt_precompute_g01(
    const float* __restrict__ core0,
    const float* __restrict__ core1)
{
    __shared__ float Bs[1024];   // core1 slice for this i2: [r1][n2*16+r2]
    __shared__ float As[640];    // core0 slices for 10 i1: [qq][n1*16+r1]

    const int i2 = blockIdx.x;
    const int g  = blockIdx.y;
    const int t  = threadIdx.x;

    #pragma unroll
    for (int j = t; j < 1024; j += 256)
        Bs[j] = core1[(j >> 6) * 6400 + i2 * 64 + (j & 63)];
    #pragma unroll
    for (int j = t; j < 640; j += 256)
        As[j] = core0[g * 640 + j];
    __syncthreads();

    const int p    = t & 127;        // output pair index
    const int half = t >> 7;         // 0/1 -> i1 offsets {0..4} / {5..9}
    const int n1   = p >> 5;         // constant per warp -> As broadcast
    const int rp   = (p & 31) * 2;   // rest pair start (n2*16+r2)

    // hoist B column (pair) into registers: reused across 5 i1's
    unsigned long long b2[16];
    #pragma unroll
    for (int r1 = 0; r1 < 16; r1++)
        b2[r1] = *(const unsigned long long*)&Bs[r1 * 64 + rp];

    #pragma unroll
    for (int qq = 0; qq < 5; qq++) {
        const int q = half * 5 + qq;
        unsigned long long acc = 0;   // (+0.0f, +0.0f)
        #pragma unroll
        for (int r1 = 0; r1 < 16; r1++)
            acc = f32x2_fma(f32x2_bcast(As[q * 64 + n1 * 16 + r1]), b2[r1], acc);
        const int i1 = g * 10 + q;
        *(unsigned long long*)&g_G01[((size_t)(i1 * 100 + i2)) * 256 + p * 2] = acc;
    }
}

// ---------------------------------------------------------------------------
// Kernel 2: gather.  1 warp per token, 4 outputs per lane.
// lane: row = lane>>1 (n1*4+n2), q = lane&1 (n3 quad).
// core2: (16,100,8,1) elem (r2,i3,n3) @ r2*800 + i3*8 + n3
// ---------------------------------------------------------------------------
__global__ void __launch_bounds__(256) tt_gather(
    const void*  __restrict__ xraw,
    const float* __restrict__ core2,
    float*       __restrict__ out,
    int n_tok)
{
    const int t    = threadIdx.x;
    const int lane = t & 31;
    const int tok  = blockIdx.x * 8 + (t >> 5);
    if (tok >= n_tok) return;

    // --- index dtype autodetect (int64 declared, but jax may emit int32) ---
    const unsigned long long* p64 = (const unsigned long long*)xraw;
    bool is64 = true;
    #pragma unroll
    for (int j = 0; j < 4; j++)
        if (p64[j] >= VOC_LL) is64 = false;

    const long long idxll = is64 ? ((const long long*)xraw)[tok]
                                 : (long long)((const int*)xraw)[tok];
    const unsigned int iv  = (unsigned int)idxll;      // < 1e6
    const unsigned int i3  = iv % 100u;
    const unsigned int i12 = iv / 100u;

    const int row = lane >> 1;   // n1*4 + n2
    const int q   = lane & 1;    // n3 in [4q, 4q+4)

    // G row: 16 floats as 4x LDG.128 (L2-resident g_G01)
    const float4* G = (const float4*)(g_G01 + (size_t)i12 * 256) + row * 4;
    const float4 g0 = G[0], g1 = G[1], g2 = G[2], g3 = G[3];
    const float gr[16] = { g0.x, g0.y, g0.z, g0.w,  g1.x, g1.y, g1.z, g1.w,
                           g2.x, g2.y, g2.z, g2.w,  g3.x, g3.y, g3.z, g3.w };

    // C: per r2 one 16B broadcast load (warp has only 2 distinct addresses)
    const char* cbase = (const char*)(core2 + (size_t)i3 * 8 + q * 4);
    unsigned long long acc0 = 0, acc1 = 0;
    #pragma unroll
    for (int r2 = 0; r2 < 16; r2++) {
        const ulonglong2 c = *(const ulonglong2*)(cbase + (size_t)r2 * 3200);
        const unsigned long long gg = f32x2_bcast(gr[r2]);
        acc0 = f32x2_fma(gg, c.x, acc0);
        acc1 = f32x2_fma(gg, c.y, acc1);
    }

    ulonglong2 res;
    res.x = acc0; res.y = acc1;
    if (iv == 0) { res.x = 0; res.y = 0; }   // PAD row
    *(ulonglong2*)(out + (size_t)tok * 128 + row * 8 + q * 4) = res;
}

// ---------------------------------------------------------------------------
extern "C" void kernel_launch(void* const* d_in, const int* in_sizes, int n_in,
                              void* d_out, int out_size)
{
    const void*  x     = d_in[0];
    const float* core0 = (const float*)d_in[1];
    const float* core1 = (const float*)d_in[2];
    const float* core2 = (const float*)d_in[3];
    float*       out   = (float*)d_out;

    const int n_tok = in_sizes[0];   // 32768

    tt_precompute_g01<<<dim3(100, 10), 256>>>(core0, core1);
    tt_gather<<<(n_tok + 7) / 8, 256>>>(x, core2, out, n_tok);
}